// round 15
// baseline (speedup 1.0000x reference)
#include <cuda_runtime.h>
#include <cuda_bf16.h>
#include <cstdint>

// ---------------------------------------------------------------------------
// GraphSAGE (3 layers, mean agg) on GB300 — R15: R13 base +
//  (1) layers 2-3 GEMM: 16 stages of K=16, 4-deep cp.async ring
//      (wait_group 2 -> 3-stage load lookahead, hides L2 latency),
//  (2) conv_w folded into k_hist, (3) warp-shuffle scan.
// Layer-1 GEMM keeps the proven R13 SPLIT_A double-buffer path.
// ---------------------------------------------------------------------------

#define NN 100000
#define NE 600000
#define NB_SCAN 98

// CSR scratch
__device__ int g_cnt[NN];
__device__ int g_rowptr[NN + 1];
__device__ unsigned long long g_state[NB_SCAN];
__device__ int g_srcs[NE];

// activations as split bf16 (hi + lo ~= fp32)
__device__ __align__(128) __nv_bfloat16 g_s0hi[(size_t)NN * 128];
__device__ __align__(128) __nv_bfloat16 g_s0lo[(size_t)NN * 128];
__device__ __align__(128) __nv_bfloat16 g_s1hi[(size_t)NN * 128];
__device__ __align__(128) __nv_bfloat16 g_s1lo[(size_t)NN * 128];
__device__ __align__(128) __nv_bfloat16 g_agghi[(size_t)NN * 128];
__device__ __align__(128) __nv_bfloat16 g_agglo[(size_t)NN * 128];

// weights split bf16, packed: Ws1,Wn1,Ws2,Wn2,Ws3,Wn3
#define WS1 0
#define WN1 16384
#define WS2 32768
#define WN2 49152
#define WS3 65536
#define WN3 73728
#define NWE 81920
__device__ __align__(128) __nv_bfloat16 g_whi[NWE];
__device__ __align__(128) __nv_bfloat16 g_wlo[NWE];

// ---------------------------- PTX helpers ---------------------------------

__device__ __forceinline__ uint32_t smem_u32(const void* p) {
    uint32_t a;
    asm("{ .reg .u64 t; cvta.to.shared.u64 t, %1; cvt.u32.u64 %0, t; }" : "=r"(a) : "l"(p));
    return a;
}
__device__ __forceinline__ void ldsm_x4(uint32_t* r, uint32_t addr) {
    asm volatile("ldmatrix.sync.aligned.m8n8.x4.shared.b16 {%0,%1,%2,%3}, [%4];"
                 : "=r"(r[0]), "=r"(r[1]), "=r"(r[2]), "=r"(r[3]) : "r"(addr));
}
__device__ __forceinline__ void mma_bf16(float* d, const uint32_t* a, const uint32_t* b) {
    asm volatile(
        "mma.sync.aligned.m16n8k16.row.col.f32.bf16.bf16.f32 "
        "{%0,%1,%2,%3}, {%4,%5,%6,%7}, {%8,%9}, {%0,%1,%2,%3};"
        : "+f"(d[0]), "+f"(d[1]), "+f"(d[2]), "+f"(d[3])
        : "r"(a[0]), "r"(a[1]), "r"(a[2]), "r"(a[3]), "r"(b[0]), "r"(b[1]));
}
__device__ __forceinline__ void cp16(uint32_t dst, const void* src, bool valid) {
    int sz = valid ? 16 : 0;
    asm volatile("cp.async.cg.shared.global [%0], [%1], 16, %2;"
                 :: "r"(dst), "l"(src), "r"(sz) : "memory");
}
#define CP_COMMIT() asm volatile("cp.async.commit_group;" ::: "memory")
#define CP_WAIT0()  asm volatile("cp.async.wait_group 0;" ::: "memory")
#define CP_WAIT2()  asm volatile("cp.async.wait_group 2;" ::: "memory")

// ---------------------------- CSR construction ----------------------------

__device__ __forceinline__ void split1(float v, __nv_bfloat16& h, __nv_bfloat16& l) {
    h = __float2bfloat16_rn(v);
    l = __float2bfloat16_rn(v - __bfloat162float(h));
}
__device__ __forceinline__ uint32_t pack2(__nv_bfloat16 a, __nv_bfloat16 b) {
    __nv_bfloat162 t;
    t.x = a; t.y = b;
    return *reinterpret_cast<uint32_t*>(&t);
}
__device__ __forceinline__ float2 upk(uint32_t w) {
    return __bfloat1622float2(*reinterpret_cast<__nv_bfloat162*>(&w));
}

// hist + weight-split fused (independent work, saves one launch)
__global__ void k_hist(const int* __restrict__ dst,
                       const float* __restrict__ ws1, const float* __restrict__ wn1,
                       const float* __restrict__ ws2, const float* __restrict__ wn2,
                       const float* __restrict__ ws3, const float* __restrict__ wn3) {
    int gi = blockIdx.x * blockDim.x + threadIdx.x;
    int e = gi * 2;
    if (e < NE) {
        int2 d = *(const int2*)(dst + e);
        atomicAdd(&g_cnt[d.x], 1);
        atomicAdd(&g_cnt[d.y], 1);
    }
    int w = gi * 4;
    if (w < NWE) {
        const float* src; int base;
        if      (w < WN1) { src = ws1; base = WS1; }
        else if (w < WS2) { src = wn1; base = WN1; }
        else if (w < WN2) { src = ws2; base = WS2; }
        else if (w < WS3) { src = wn2; base = WN2; }
        else if (w < WN3) { src = ws3; base = WS3; }
        else              { src = wn3; base = WN3; }
        float4 v = *(const float4*)(src + (w - base));
        __nv_bfloat16 h0, h1, h2, h3, l0, l1, l2, l3;
        split1(v.x, h0, l0); split1(v.y, h1, l1); split1(v.z, h2, l2); split1(v.w, h3, l3);
        *(uint2*)(g_whi + w) = make_uint2(pack2(h0, h1), pack2(h2, h3));
        *(uint2*)(g_wlo + w) = make_uint2(pack2(l0, l1), pack2(l2, l3));
    }
}

__global__ void k_scan() {
    __shared__ int sh_w[32];
    __shared__ int s_prefix;
    const int t = threadIdx.x, b = blockIdx.x;
    const int lane = t & 31, wid = t >> 5;
    const int i = b * 1024 + t;
    int v = (i < NN) ? g_cnt[i] : 0;
    int sc = v;
#pragma unroll
    for (int o = 1; o < 32; o <<= 1) {
        int y = __shfl_up_sync(0xffffffffu, sc, o);
        if (lane >= o) sc += y;
    }
    if (lane == 31) sh_w[wid] = sc;
    __syncthreads();
    if (wid == 0) {
        int w = sh_w[lane];
#pragma unroll
        for (int o = 1; o < 32; o <<= 1) {
            int y = __shfl_up_sync(0xffffffffu, w, o);
            if (lane >= o) w += y;
        }
        sh_w[lane] = w;
    }
    __syncthreads();
    int blk_incl = sc + (wid ? sh_w[wid - 1] : 0);
    if (t == 1023)
        atomicExch(&g_state[b], (1ULL << 32) | (unsigned)blk_incl);
    if (t < 32) {
        int run = 0;
        for (int base = b - 1; base >= 0; base -= 32) {
            int idx = base - t;
            unsigned val = 0;
            if (idx >= 0) {
                unsigned long long w;
                do { w = atomicAdd(&g_state[idx], 0ULL); } while ((w >> 32) == 0);
                val = (unsigned)w;
            }
#pragma unroll
            for (int o = 16; o; o >>= 1) val += __shfl_xor_sync(0xffffffffu, val, o);
            run += (int)val;
        }
        if (t == 0) s_prefix = run;
    }
    __syncthreads();
    int prefix = s_prefix;
    if (i < NN) {
        g_rowptr[i + 1] = prefix + blk_incl;
        g_cnt[i] = 0;
    }
    if (i == 0) g_rowptr[0] = 0;
}
__global__ void k_scatter(const int* __restrict__ src, const int* __restrict__ dst) {
    int e = (blockIdx.x * blockDim.x + threadIdx.x) * 2;
    if (e < NE) {
        int2 d = *(const int2*)(dst + e);
        int2 s = *(const int2*)(src + e);
        int p0 = g_rowptr[d.x] + atomicAdd(&g_cnt[d.x], 1);
        int p1 = g_rowptr[d.y] + atomicAdd(&g_cnt[d.y], 1);
        g_srcs[p0] = s.x;
        g_srcs[p1] = s.y;
    }
}

// ---------------------------- segment mean --------------------------------

__global__ void k_agg_f32(const float* __restrict__ hf,
                          __nv_bfloat16* __restrict__ ahi,
                          __nv_bfloat16* __restrict__ alo) {
    int gw = (blockIdx.x * blockDim.x + threadIdx.x) >> 5;
    int lane = threadIdx.x & 31;
    if (gw >= NN) return;
    const int s = g_rowptr[gw];
    const int e = g_rowptr[gw + 1];
    float a0 = 0.f, a1 = 0.f, a2 = 0.f, a3 = 0.f;
    int j = s;
    for (; j + 1 < e; j += 2) {
        int s0 = g_srcs[j], s1 = g_srcs[j + 1];
        float4 v0 = *(const float4*)(hf + (((size_t)s0) << 7) + lane * 4);
        float4 v1 = *(const float4*)(hf + (((size_t)s1) << 7) + lane * 4);
        a0 += v0.x + v1.x; a1 += v0.y + v1.y;
        a2 += v0.z + v1.z; a3 += v0.w + v1.w;
    }
    if (j < e) {
        float4 v = *(const float4*)(hf + (((size_t)g_srcs[j]) << 7) + lane * 4);
        a0 += v.x; a1 += v.y; a2 += v.z; a3 += v.w;
    }
    float inv = 1.0f / (float)max(e - s, 1);
    a0 *= inv; a1 *= inv; a2 *= inv; a3 *= inv;
    __nv_bfloat16 h0, h1, h2, h3, l0, l1, l2, l3;
    split1(a0, h0, l0); split1(a1, h1, l1); split1(a2, h2, l2); split1(a3, h3, l3);
    size_t o = (((size_t)gw) << 7) + lane * 4;
    *(uint2*)(ahi + o) = make_uint2(pack2(h0, h1), pack2(h2, h3));
    *(uint2*)(alo + o) = make_uint2(pack2(l0, l1), pack2(l2, l3));
}

__global__ void k_agg_split(const __nv_bfloat16* __restrict__ hhi,
                            const __nv_bfloat16* __restrict__ hlo,
                            __nv_bfloat16* __restrict__ ahi,
                            __nv_bfloat16* __restrict__ alo) {
    int gw = (blockIdx.x * blockDim.x + threadIdx.x) >> 5;
    int lane = threadIdx.x & 31;
    if (gw >= NN) return;
    const int s = g_rowptr[gw];
    const int e = g_rowptr[gw + 1];
    const __nv_bfloat16* base = (lane < 16) ? hhi : hlo;
    const int f0 = (lane & 15) * 8;
    float a[8];
#pragma unroll
    for (int q = 0; q < 8; q++) a[q] = 0.f;
    int j = s;
    for (; j + 1 < e; j += 2) {
        int s0 = g_srcs[j], s1 = g_srcs[j + 1];
        uint4 v0 = *(const uint4*)(base + (((size_t)s0) << 7) + f0);
        uint4 v1 = *(const uint4*)(base + (((size_t)s1) << 7) + f0);
        float2 p;
        p = upk(v0.x); a[0] += p.x; a[1] += p.y;
        p = upk(v0.y); a[2] += p.x; a[3] += p.y;
        p = upk(v0.z); a[4] += p.x; a[5] += p.y;
        p = upk(v0.w); a[6] += p.x; a[7] += p.y;
        p = upk(v1.x); a[0] += p.x; a[1] += p.y;
        p = upk(v1.y); a[2] += p.x; a[3] += p.y;
        p = upk(v1.z); a[4] += p.x; a[5] += p.y;
        p = upk(v1.w); a[6] += p.x; a[7] += p.y;
    }
    if (j < e) {
        uint4 v0 = *(const uint4*)(base + (((size_t)g_srcs[j]) << 7) + f0);
        float2 p;
        p = upk(v0.x); a[0] += p.x; a[1] += p.y;
        p = upk(v0.y); a[2] += p.x; a[3] += p.y;
        p = upk(v0.z); a[4] += p.x; a[5] += p.y;
        p = upk(v0.w); a[6] += p.x; a[7] += p.y;
    }
#pragma unroll
    for (int q = 0; q < 8; q++) a[q] += __shfl_xor_sync(0xffffffffu, a[q], 16);
    if (lane < 16) {
        float inv = 1.0f / (float)max(e - s, 1);
        __nv_bfloat16 h[8], l[8];
#pragma unroll
        for (int q = 0; q < 8; q++) split1(a[q] * inv, h[q], l[q]);
        size_t o = (((size_t)gw) << 7) + f0;
        *(uint4*)(ahi + o) = make_uint4(pack2(h[0], h[1]), pack2(h[2], h[3]),
                                        pack2(h[4], h[5]), pack2(h[6], h[7]));
        *(uint4*)(alo + o) = make_uint4(pack2(l[0], l[1]), pack2(l[2], l[3]),
                                        pack2(l[4], l[5]), pack2(l[6], l[7]));
    }
}

// ---------------------------- GEMM (layer 1, R13 path) --------------------
// 128 threads, warp tile 64x64, K=256 as 8 K=32 stages, 2-deep, SPLIT_A.

template <int DOUT, bool RELU, bool SPLIT_OUT>
__global__ void __launch_bounds__(128, 2)
k_gemm2(const float* __restrict__ xf,
        const __nv_bfloat16* __restrict__ ghi, const __nv_bfloat16* __restrict__ glo,
        const __nv_bfloat16* __restrict__ wshi, const __nv_bfloat16* __restrict__ wslo,
        const __nv_bfloat16* __restrict__ wnhi, const __nv_bfloat16* __restrict__ wnlo,
        const float* __restrict__ bias,
        float* __restrict__ outf,
        __nv_bfloat16* __restrict__ ohi, __nv_bfloat16* __restrict__ olo) {
    extern __shared__ char sm[];
    constexpr int WARP_N = DOUT / 2;
    constexpr int NT = WARP_N / 8;
    constexpr int A_B = 128 * 80;
    constexpr int B_B = DOUT * 80;
    constexpr int STG = 2 * A_B + 2 * B_B;

    const int tid = threadIdx.x, wid = tid >> 5, lane = tid & 31;
    const int wm = wid & 1, wn = wid >> 1;
    const int row0 = blockIdx.x * 128;
    const uint32_t sb = smem_u32(sm);

    float acc[4][NT][4];
#pragma unroll
    for (int mt = 0; mt < 4; mt++)
#pragma unroll
        for (int nt = 0; nt < NT; nt++)
#pragma unroll
            for (int q = 0; q < 4; q++) acc[mt][nt][q] = 0.f;

    float xr[32];

    auto loadB = [&](int s, int p) {
        const int koff = (s & 3) * 32;
        const __nv_bfloat16* Bh = (s < 4) ? wshi : wnhi;
        const __nv_bfloat16* Bl = (s < 4) ? wslo : wnlo;
        const uint32_t bh = sb + p * STG + 2 * A_B, bl = bh + B_B;
#pragma unroll
        for (int i = 0; i < DOUT / 32; i++) {
            int c = i * 128 + tid;
            int r = c >> 2, kc = c & 3;
            size_t off = ((size_t)r << 7) + koff + kc * 8;
            cp16(bh + r * 80 + kc * 16, Bh + off, true);
            cp16(bl + r * 80 + kc * 16, Bl + off, true);
        }
    };
    auto loadA = [&](int s, int p) {
        const int koff = (s & 3) * 32;
        const uint32_t ah = sb + p * STG, al = ah + A_B;
#pragma unroll
        for (int i = 0; i < 4; i++) {
            int c = i * 128 + tid;
            int r = c >> 2, kc = c & 3;
            bool v = (row0 + r) < NN;
            size_t off = ((size_t)(row0 + r) << 7) + koff + kc * 8;
            cp16(ah + r * 80 + kc * 16, ghi + off, v);
            cp16(al + r * 80 + kc * 16, glo + off, v);
        }
    };
    auto ldgA = [&](int s) {
        const int koff = (s & 3) * 32;
#pragma unroll
        for (int i = 0; i < 8; i++) {
            int c = i * 128 + tid;
            int r = c >> 3, q = c & 7;
            float4 t = make_float4(0.f, 0.f, 0.f, 0.f);
            if (row0 + r < NN)
                t = *(const float4*)(xf + ((size_t)(row0 + r) << 7) + koff + q * 4);
            xr[i * 4 + 0] = t.x; xr[i * 4 + 1] = t.y;
            xr[i * 4 + 2] = t.z; xr[i * 4 + 3] = t.w;
        }
    };
    auto stsA = [&](int p) {
        const uint32_t ah = sb + p * STG, al = ah + A_B;
#pragma unroll
        for (int i = 0; i < 8; i++) {
            int c = i * 128 + tid;
            int r = c >> 3, q = c & 7;
            __nv_bfloat16 h0, h1, h2, h3, l0, l1, l2, l3;
            split1(xr[i * 4 + 0], h0, l0); split1(xr[i * 4 + 1], h1, l1);
            split1(xr[i * 4 + 2], h2, l2); split1(xr[i * 4 + 3], h3, l3);
            uint32_t hh0 = pack2(h0, h1), hh1 = pack2(h2, h3);
            uint32_t ll0 = pack2(l0, l1), ll1 = pack2(l2, l3);
            uint32_t d = r * 80 + q * 8;
            asm volatile("st.shared.v2.b32 [%0], {%1,%2};" :: "r"(ah + d), "r"(hh0), "r"(hh1) : "memory");
            asm volatile("st.shared.v2.b32 [%0], {%1,%2};" :: "r"(al + d), "r"(ll0), "r"(ll1) : "memory");
        }
    };
    auto compute = [&](int p) {
#pragma unroll
        for (int ks = 0; ks < 2; ks++) {
            uint32_t ahf[4][4], alf[4][4];
#pragma unroll
            for (int mt = 0; mt < 4; mt++) {
                int r = wm * 64 + mt * 16 + (lane & 15);
                int kc = ks * 2 + (lane >> 4);
                uint32_t o = p * STG + (uint32_t)(r * 80) + (uint32_t)(kc * 16);
                ldsm_x4(ahf[mt], sb + o);
                ldsm_x4(alf[mt], sb + A_B + o);
            }
#pragma unroll
            for (int np = 0; np < NT / 2; np++) {
                int n = wn * WARP_N + np * 16 + (lane & 7) + ((lane >> 4) << 3);
                int kc = ks * 2 + ((lane >> 3) & 1);
                uint32_t o = p * STG + 2 * A_B + (uint32_t)(n * 80) + (uint32_t)(kc * 16);
                uint32_t bh[4], bl[4];
                ldsm_x4(bh, sb + o);
                ldsm_x4(bl, sb + B_B + o);
#pragma unroll
                for (int mt = 0; mt < 4; mt++) {
                    mma_bf16(acc[mt][2 * np],     ahf[mt], bh);
                    mma_bf16(acc[mt][2 * np + 1], ahf[mt], bh + 2);
                }
#pragma unroll
                for (int mt = 0; mt < 4; mt++) {
                    mma_bf16(acc[mt][2 * np],     alf[mt], bh);
                    mma_bf16(acc[mt][2 * np + 1], alf[mt], bh + 2);
                }
#pragma unroll
                for (int mt = 0; mt < 4; mt++) {
                    mma_bf16(acc[mt][2 * np],     ahf[mt], bl);
                    mma_bf16(acc[mt][2 * np + 1], ahf[mt], bl + 2);
                }
            }
        }
    };

    loadB(0, 0);
    ldgA(0); stsA(0);
    CP_COMMIT();
    CP_WAIT0();
    __syncthreads();

    int p = 0;
#pragma unroll
    for (int s = 0; s < 8; s++) {
        const int sn = s + 1;
        if (sn < 8) {
            loadB(sn, p ^ 1);
            if (sn < 4) ldgA(sn);
            else loadA(sn, p ^ 1);
            CP_COMMIT();
        }
        compute(p);
        if (sn < 8) {
            if (sn < 4) stsA(p ^ 1);
            CP_WAIT0();
            __syncthreads();
            p ^= 1;
        }
    }

    const int g = lane >> 2, t = lane & 3;
#pragma unroll
    for (int mt = 0; mt < 4; mt++) {
        int r0 = row0 + wm * 64 + mt * 16 + g;
        int r1 = r0 + 8;
#pragma unroll
        for (int nt = 0; nt < NT; nt++) {
            int col = wn * WARP_N + nt * 8 + 2 * t;
            float b0 = __ldg(bias + col), b1 = __ldg(bias + col + 1);
            float c0 = acc[mt][nt][0] + b0, c1 = acc[mt][nt][1] + b1;
            float c2 = acc[mt][nt][2] + b0, c3 = acc[mt][nt][3] + b1;
            if (RELU) {
                c0 = fmaxf(c0, 0.f); c1 = fmaxf(c1, 0.f);
                c2 = fmaxf(c2, 0.f); c3 = fmaxf(c3, 0.f);
            }
            if (SPLIT_OUT) {
                __nv_bfloat16 h0, h1, l0, l1;
                if (r0 < NN) {
                    split1(c0, h0, l0); split1(c1, h1, l1);
                    size_t o = ((size_t)r0 << 7) + col;
                    *(uint32_t*)(ohi + o) = pack2(h0, h1);
                    *(uint32_t*)(olo + o) = pack2(l0, l1);
                }
                if (r1 < NN) {
                    split1(c2, h0, l0); split1(c3, h1, l1);
                    size_t o = ((size_t)r1 << 7) + col;
                    *(uint32_t*)(ohi + o) = pack2(h0, h1);
                    *(uint32_t*)(olo + o) = pack2(l0, l1);
                }
            } else {
                if (r0 < NN) *(float2*)(outf + (size_t)r0 * DOUT + col) = make_float2(c0, c1);
                if (r1 < NN) *(float2*)(outf + (size_t)r1 * DOUT + col) = make_float2(c2, c3);
            }
        }
    }
}

// ---------------------------- GEMM deep-pipe (layers 2-3) -----------------
// 128 threads, warp tile 64x(DOUT/2). K=256 as 16 stages of K=16, 4-deep
// cp.async ring with wait_group 2 (3 stages of loads in flight).
// Rows 48B stride (2x16B chunks + 16B pad): conflict-free ldsm.
// Loop body: wait_group 2 -> syncthreads -> issue load(s+3) -> compute(s).
// The barrier retires compute(s-1) before buffer (s+3)%4 == (s-1)%4 reuse.

template <int DOUT, bool RELU, bool SPLIT_OUT>
__global__ void __launch_bounds__(128, 2)
k_gemm4(const __nv_bfloat16* __restrict__ ahi, const __nv_bfloat16* __restrict__ alo,
        const __nv_bfloat16* __restrict__ ghi, const __nv_bfloat16* __restrict__ glo,
        const __nv_bfloat16* __restrict__ wshi, const __nv_bfloat16* __restrict__ wslo,
        const __nv_bfloat16* __restrict__ wnhi, const __nv_bfloat16* __restrict__ wnlo,
        const float* __restrict__ bias,
        float* __restrict__ outf,
        __nv_bfloat16* __restrict__ ohi, __nv_bfloat16* __restrict__ olo) {
    extern __shared__ char sm[];
    constexpr int WARP_N = DOUT / 2;
    constexpr int NT = WARP_N / 8;
    constexpr int NP = NT / 2;
    constexpr int A_B = 128 * 48;
    constexpr int B_B = DOUT * 48;
    constexpr int STG = 2 * A_B + 2 * B_B;

    const int tid = threadIdx.x, wid = tid >> 5, lane = tid & 31;
    const int wm = wid & 1, wn = wid >> 1;
    const int row0 = blockIdx.x * 128;
    const uint32_t sb = smem_u32(sm);

    float acc[4][NT][4];
#pragma unroll
    for (int mt = 0; mt < 4; mt++)
#pragma unroll
        for (int nt = 0; nt < NT; nt++)
#pragma unroll
            for (int q = 0; q < 4; q++) acc[mt][nt][q] = 0.f;

    // stage s: K-offset (s&7)*16, operand select s<8 ? (self,Ws) : (agg,Wn)
    auto loadStage = [&](int s) {
        const int p = s & 3;
        const int koff = (s & 7) * 16;
        const __nv_bfloat16* Ah = (s < 8) ? ahi : ghi;
        const __nv_bfloat16* Al = (s < 8) ? alo : glo;
        const __nv_bfloat16* Bh = (s < 8) ? wshi : wnhi;
        const __nv_bfloat16* Bl = (s < 8) ? wslo : wnlo;
        const uint32_t ah = sb + p * STG, al = ah + A_B;
        const uint32_t bh = al + A_B, bl = bh + B_B;
        // A: 128 rows x 2 chunks = 256 cp16 per array -> 2 per thread
#pragma unroll
        for (int i = 0; i < 2; i++) {
            int c = i * 128 + tid;
            int r = c >> 1, kc = c & 1;
            bool v = (row0 + r) < NN;
            size_t off = ((size_t)(row0 + r) << 7) + koff + kc * 8;
            cp16(ah + r * 48 + kc * 16, Ah + off, v);
            cp16(al + r * 48 + kc * 16, Al + off, v);
        }
        // B: DOUT rows x 2 chunks
#pragma unroll
        for (int i = 0; i < DOUT / 64; i++) {
            int c = i * 128 + tid;
            int r = c >> 1, kc = c & 1;
            size_t off = ((size_t)r << 7) + koff + kc * 8;
            cp16(bh + r * 48 + kc * 16, Bh + off, true);
            cp16(bl + r * 48 + kc * 16, Bl + off, true);
        }
        CP_COMMIT();
    };
    auto compute = [&](int s) {
        const int p = s & 3;
        uint32_t ahf[4][4], alf[4][4];
#pragma unroll
        for (int mt = 0; mt < 4; mt++) {
            int r = wm * 64 + mt * 16 + (lane & 15);
            int kc = lane >> 4;
            uint32_t o = p * STG + (uint32_t)(r * 48) + (uint32_t)(kc * 16);
            ldsm_x4(ahf[mt], sb + o);
            ldsm_x4(alf[mt], sb + A_B + o);
        }
#pragma unroll
        for (int np = 0; np < NP; np++) {
            int n = wn * WARP_N + np * 16 + (lane & 7) + ((lane >> 4) << 3);
            int kc = (lane >> 3) & 1;
            uint32_t o = p * STG + 2 * A_B + (uint32_t)(n * 48) + (uint32_t)(kc * 16);
            uint32_t bh[4], bl[4];
            ldsm_x4(bh, sb + o);
            ldsm_x4(bl, sb + B_B + o);
#pragma unroll
            for (int mt = 0; mt < 4; mt++) {
                mma_bf16(acc[mt][2 * np],     ahf[mt], bh);
                mma_bf16(acc[mt][2 * np + 1], ahf[mt], bh + 2);
            }
#pragma unroll
            for (int mt = 0; mt < 4; mt++) {
                mma_bf16(acc[mt][2 * np],     alf[mt], bh);
                mma_bf16(acc[mt][2 * np + 1], alf[mt], bh + 2);
            }
#pragma unroll
            for (int mt = 0; mt < 4; mt++) {
                mma_bf16(acc[mt][2 * np],     ahf[mt], bl);
                mma_bf16(acc[mt][2 * np + 1], ahf[mt], bl + 2);
            }
        }
    };

    // prologue: 3 stages in flight
    loadStage(0);
    loadStage(1);
    loadStage(2);

#pragma unroll
    for (int s = 0; s < 16; s++) {
        CP_WAIT2();          // stage s landed (<=2 younger groups outstanding)
        __syncthreads();     // all threads' data visible; compute(s-1) retired
        if (s + 3 < 16) loadStage(s + 3);  // overwrites buffer of compute(s-1)
        compute(s);
    }

    const int g = lane >> 2, t = lane & 3;
#pragma unroll
    for (int mt = 0; mt < 4; mt++) {
        int r0 = row0 + wm * 64 + mt * 16 + g;
        int r1 = r0 + 8;
#pragma unroll
        for (int nt = 0; nt < NT; nt++) {
            int col = wn * WARP_N + nt * 8 + 2 * t;
            float b0 = __ldg(bias + col), b1 = __ldg(bias + col + 1);
            float c0 = acc[mt][nt][0] + b0, c1 = acc[mt][nt][1] + b1;
            float c2 = acc[mt][nt][2] + b0, c3 = acc[mt][nt][3] + b1;
            if (RELU) {
                c0 = fmaxf(c0, 0.f); c1 = fmaxf(c1, 0.f);
                c2 = fmaxf(c2, 0.f); c3 = fmaxf(c3, 0.f);
            }
            if (SPLIT_OUT) {
                __nv_bfloat16 h0, h1, l0, l1;
                if (r0 < NN) {
                    split1(c0, h0, l0); split1(c1, h1, l1);
                    size_t o = ((size_t)r0 << 7) + col;
                    *(uint32_t*)(ohi + o) = pack2(h0, h1);
                    *(uint32_t*)(olo + o) = pack2(l0, l1);
                }
                if (r1 < NN) {
                    split1(c2, h0, l0); split1(c3, h1, l1);
                    size_t o = ((size_t)r1 << 7) + col;
                    *(uint32_t*)(ohi + o) = pack2(h0, h1);
                    *(uint32_t*)(olo + o) = pack2(l0, l1);
                }
            } else {
                if (r0 < NN) *(float2*)(outf + (size_t)r0 * DOUT + col) = make_float2(c0, c1);
                if (r1 < NN) *(float2*)(outf + (size_t)r1 * DOUT + col) = make_float2(c2, c3);
            }
        }
    }
}

// ---------------------------------------------------------------------------

extern "C" void kernel_launch(void* const* d_in, const int* in_sizes, int n_in,
                              void* d_out, int out_size) {
    const float* x   = (const float*)d_in[0];
    const int* esrc  = (const int*)d_in[1];
    const int* edst  = (const int*)d_in[2];
    const float* Ws1 = (const float*)d_in[3];
    const float* Wn1 = (const float*)d_in[4];
    const float* b1  = (const float*)d_in[5];
    const float* Ws2 = (const float*)d_in[6];
    const float* Wn2 = (const float*)d_in[7];
    const float* b2  = (const float*)d_in[8];
    const float* Ws3 = (const float*)d_in[9];
    const float* Wn3 = (const float*)d_in[10];
    const float* b3  = (const float*)d_in[11];
    float* out = (float*)d_out;

    __nv_bfloat16 *s0hi, *s0lo, *s1hi, *s1lo, *aghi, *aglo, *whi, *wlo;
    cudaGetSymbolAddress((void**)&s0hi, g_s0hi);
    cudaGetSymbolAddress((void**)&s0lo, g_s0lo);
    cudaGetSymbolAddress((void**)&s1hi, g_s1hi);
    cudaGetSymbolAddress((void**)&s1lo, g_s1lo);
    cudaGetSymbolAddress((void**)&aghi, g_agghi);
    cudaGetSymbolAddress((void**)&aglo, g_agglo);
    cudaGetSymbolAddress((void**)&whi, g_whi);
    cudaGetSymbolAddress((void**)&wlo, g_wlo);

    int *cnt; unsigned long long *state;
    cudaGetSymbolAddress((void**)&cnt, g_cnt);
    cudaGetSymbolAddress((void**)&state, g_state);

    const int SMEM_1  = 2 * (2 * 128 * 80 + 2 * 128 * 80);  // 81920 (gemm2)
    const int SMEM_2  = 4 * (2 * 128 * 48 + 2 * 128 * 48);  // 98304 (gemm4/128)
    const int SMEM_3  = 4 * (2 * 128 * 48 + 2 * 64 * 48);   // 73728 (gemm4/64)
    cudaFuncSetAttribute(k_gemm2<128, true, true>,
                         cudaFuncAttributeMaxDynamicSharedMemorySize, SMEM_1);
    cudaFuncSetAttribute(k_gemm4<128, true, true>,
                         cudaFuncAttributeMaxDynamicSharedMemorySize, SMEM_2);
    cudaFuncSetAttribute(k_gemm4<64, false, false>,
                         cudaFuncAttributeMaxDynamicSharedMemorySize, SMEM_3);

    const int TB = 256;
    const int gridE2 = (NE / 2 + TB - 1) / TB;
    const int gridW = (NN * 32 + TB - 1) / TB;
    const int gridM = (NN + 127) / 128;  // 782

    // CSR build
    cudaMemsetAsync(cnt, 0, NN * sizeof(int));
    cudaMemsetAsync(state, 0, NB_SCAN * sizeof(unsigned long long));
    k_hist<<<gridE2, TB>>>(edst, Ws1, Wn1, Ws2, Wn2, Ws3, Wn3);  // #1 (+conv_w)
    k_scan<<<NB_SCAN, 1024>>>();                                 // #2
    k_scatter<<<gridE2, TB>>>(esrc, edst);                       // #3

    // Layer-1 agg — kernel #4 (ncu capture slot)
    k_agg_f32<<<gridW, TB>>>(x, aghi, aglo);

    // Layer 1 (SPLIT_A inline fp32 self path, R13-proven)
    k_gemm2<128, true, true><<<gridM, 128, SMEM_1>>>(
        x, aghi, aglo,
        whi + WS1, wlo + WS1, whi + WN1, wlo + WN1, b1,
        nullptr, s1hi, s1lo);

    // Layer 2 (deep-pipe GEMM)
    k_agg_split<<<gridW, TB>>>(s1hi, s1lo, aghi, aglo);
    k_gemm4<128, true, true><<<gridM, 128, SMEM_2>>>(
        s1hi, s1lo, aghi, aglo,
        whi + WS2, wlo + WS2, whi + WN2, wlo + WN2, b2,
        nullptr, s0hi, s0lo);

    // Layer 3 (deep-pipe GEMM, fp32 out)
    k_agg_split<<<gridW, TB>>>(s0hi, s0lo, aghi, aglo);
    k_gemm4<64, false, false><<<gridM, 128, SMEM_3>>>(
        s0hi, s0lo, aghi, aglo,
        whi + WS3, wlo + WS3, whi + WN3, wlo + WN3, b3,
        out, nullptr, nullptr);
}

// round 16
// speedup vs baseline: 1.0581x; 1.0581x over previous
#include <cuda_runtime.h>
#include <cuda_fp16.h>
#include <cstdint>

// ---------------------------------------------------------------------------
// GraphSAGE (3 layers, mean agg) on GB300 — R16: R13 config with fp16 2-term
// split GEMM: A = hi+lo fp16 (exact to ~2^-22), B = single fp16 (~2^-11).
// HMMA count -33% vs 3-term bf16; B lo arrays/loads deleted.
// ---------------------------------------------------------------------------

#define NN 100000
#define NE 600000
#define NB_SCAN 98

// CSR scratch
__device__ int g_cnt[NN];
__device__ int g_rowptr[NN + 1];
__device__ unsigned long long g_state[NB_SCAN];
__device__ int g_srcs[NE];

// activations as split fp16 (hi + lo ~= fp32)
__device__ __align__(128) __half g_s0hi[(size_t)NN * 128];
__device__ __align__(128) __half g_s0lo[(size_t)NN * 128];
__device__ __align__(128) __half g_s1hi[(size_t)NN * 128];
__device__ __align__(128) __half g_s1lo[(size_t)NN * 128];
__device__ __align__(128) __half g_agghi[(size_t)NN * 128];
__device__ __align__(128) __half g_agglo[(size_t)NN * 128];

// weights single fp16, packed: Ws1,Wn1,Ws2,Wn2,Ws3,Wn3
#define WS1 0
#define WN1 16384
#define WS2 32768
#define WN2 49152
#define WS3 65536
#define WN3 73728
#define NWE 81920
__device__ __align__(128) __half g_wh[NWE];

// ---------------------------- PTX helpers ---------------------------------

__device__ __forceinline__ uint32_t smem_u32(const void* p) {
    uint32_t a;
    asm("{ .reg .u64 t; cvta.to.shared.u64 t, %1; cvt.u32.u64 %0, t; }" : "=r"(a) : "l"(p));
    return a;
}
__device__ __forceinline__ void ldsm_x4(uint32_t* r, uint32_t addr) {
    asm volatile("ldmatrix.sync.aligned.m8n8.x4.shared.b16 {%0,%1,%2,%3}, [%4];"
                 : "=r"(r[0]), "=r"(r[1]), "=r"(r[2]), "=r"(r[3]) : "r"(addr));
}
__device__ __forceinline__ void mma_f16(float* d, const uint32_t* a, const uint32_t* b) {
    asm volatile(
        "mma.sync.aligned.m16n8k16.row.col.f32.f16.f16.f32 "
        "{%0,%1,%2,%3}, {%4,%5,%6,%7}, {%8,%9}, {%0,%1,%2,%3};"
        : "+f"(d[0]), "+f"(d[1]), "+f"(d[2]), "+f"(d[3])
        : "r"(a[0]), "r"(a[1]), "r"(a[2]), "r"(a[3]), "r"(b[0]), "r"(b[1]));
}
__device__ __forceinline__ void cp16(uint32_t dst, const void* src, bool valid) {
    int sz = valid ? 16 : 0;
    asm volatile("cp.async.cg.shared.global [%0], [%1], 16, %2;"
                 :: "r"(dst), "l"(src), "r"(sz) : "memory");
}
#define CP_COMMIT() asm volatile("cp.async.commit_group;" ::: "memory")
#define CP_WAIT0()  asm volatile("cp.async.wait_group 0;" ::: "memory")

// ---------------------------- CSR construction ----------------------------

__global__ void k_hist(const int* __restrict__ dst) {
    int e = (blockIdx.x * blockDim.x + threadIdx.x) * 2;
    if (e < NE) {
        int2 d = *(const int2*)(dst + e);
        atomicAdd(&g_cnt[d.x], 1);
        atomicAdd(&g_cnt[d.y], 1);
    }
}
__global__ void k_scan() {
    __shared__ int sh[1024];
    __shared__ int s_prefix;
    const int t = threadIdx.x, b = blockIdx.x;
    const int i = b * 1024 + t;
    int v = (i < NN) ? g_cnt[i] : 0;
    sh[t] = v;
    __syncthreads();
#pragma unroll
    for (int off = 1; off < 1024; off <<= 1) {
        int x = (t >= off) ? sh[t - off] : 0;
        __syncthreads();
        sh[t] += x;
        __syncthreads();
    }
    if (t == 1023)
        atomicExch(&g_state[b], (1ULL << 32) | (unsigned)sh[1023]);
    if (t < 32) {
        int run = 0;
        for (int base = b - 1; base >= 0; base -= 32) {
            int idx = base - t;
            unsigned val = 0;
            if (idx >= 0) {
                unsigned long long w;
                do { w = atomicAdd(&g_state[idx], 0ULL); } while ((w >> 32) == 0);
                val = (unsigned)w;
            }
#pragma unroll
            for (int o = 16; o; o >>= 1) val += __shfl_xor_sync(0xffffffffu, val, o);
            run += (int)val;
        }
        if (t == 0) s_prefix = run;
    }
    __syncthreads();
    int prefix = s_prefix;
    if (i < NN) {
        g_rowptr[i + 1] = prefix + sh[t];
        g_cnt[i] = 0;
    }
    if (i == 0) g_rowptr[0] = 0;
}
__global__ void k_scatter(const int* __restrict__ src, const int* __restrict__ dst) {
    int e = (blockIdx.x * blockDim.x + threadIdx.x) * 2;
    if (e < NE) {
        int2 d = *(const int2*)(dst + e);
        int2 s = *(const int2*)(src + e);
        int p0 = g_rowptr[d.x] + atomicAdd(&g_cnt[d.x], 1);
        int p1 = g_rowptr[d.y] + atomicAdd(&g_cnt[d.y], 1);
        g_srcs[p0] = s.x;
        g_srcs[p1] = s.y;
    }
}

// ---------------------------- conversions ---------------------------------

__device__ __forceinline__ void split1(float v, __half& h, __half& l) {
    h = __float2half_rn(v);
    l = __float2half_rn(v - __half2float(h));
}
__device__ __forceinline__ uint32_t pack2(__half a, __half b) {
    __half2 t;
    t.x = a; t.y = b;
    return *reinterpret_cast<uint32_t*>(&t);
}
__device__ __forceinline__ float2 upk(uint32_t w) {
    return __half22float2(*reinterpret_cast<__half2*>(&w));
}

__global__ void k_conv_w(const float* __restrict__ ws1, const float* __restrict__ wn1,
                         const float* __restrict__ ws2, const float* __restrict__ wn2,
                         const float* __restrict__ ws3, const float* __restrict__ wn3) {
    int i = blockIdx.x * blockDim.x + threadIdx.x;
    int e = i * 4;
    if (e >= NWE) return;
    const float* src; int base;
    if      (e < WN1) { src = ws1; base = WS1; }
    else if (e < WS2) { src = wn1; base = WN1; }
    else if (e < WN2) { src = ws2; base = WS2; }
    else if (e < WS3) { src = wn2; base = WN2; }
    else if (e < WN3) { src = ws3; base = WS3; }
    else              { src = wn3; base = WN3; }
    float4 v = *(const float4*)(src + (e - base));
    __half h0 = __float2half_rn(v.x), h1 = __float2half_rn(v.y);
    __half h2 = __float2half_rn(v.z), h3 = __float2half_rn(v.w);
    *(uint2*)(g_wh + e) = make_uint2(pack2(h0, h1), pack2(h2, h3));
}

// ---------------------------- segment mean --------------------------------

__global__ void k_agg_f32(const float* __restrict__ hf,
                          __half* __restrict__ ahi,
                          __half* __restrict__ alo) {
    int gw = (blockIdx.x * blockDim.x + threadIdx.x) >> 5;
    int lane = threadIdx.x & 31;
    if (gw >= NN) return;
    const int s = g_rowptr[gw];
    const int e = g_rowptr[gw + 1];
    float a0 = 0.f, a1 = 0.f, a2 = 0.f, a3 = 0.f;
    int j = s;
    for (; j + 1 < e; j += 2) {
        int s0 = g_srcs[j], s1 = g_srcs[j + 1];
        float4 v0 = *(const float4*)(hf + (((size_t)s0) << 7) + lane * 4);
        float4 v1 = *(const float4*)(hf + (((size_t)s1) << 7) + lane * 4);
        a0 += v0.x + v1.x; a1 += v0.y + v1.y;
        a2 += v0.z + v1.z; a3 += v0.w + v1.w;
    }
    if (j < e) {
        float4 v = *(const float4*)(hf + (((size_t)g_srcs[j]) << 7) + lane * 4);
        a0 += v.x; a1 += v.y; a2 += v.z; a3 += v.w;
    }
    float inv = 1.0f / (float)max(e - s, 1);
    a0 *= inv; a1 *= inv; a2 *= inv; a3 *= inv;
    __half h0, h1, h2, h3, l0, l1, l2, l3;
    split1(a0, h0, l0); split1(a1, h1, l1); split1(a2, h2, l2); split1(a3, h3, l3);
    size_t o = (((size_t)gw) << 7) + lane * 4;
    *(uint2*)(ahi + o) = make_uint2(pack2(h0, h1), pack2(h2, h3));
    *(uint2*)(alo + o) = make_uint2(pack2(l0, l1), pack2(l2, l3));
}

__global__ void k_agg_split(const __half* __restrict__ hhi,
                            const __half* __restrict__ hlo,
                            __half* __restrict__ ahi,
                            __half* __restrict__ alo) {
    int gw = (blockIdx.x * blockDim.x + threadIdx.x) >> 5;
    int lane = threadIdx.x & 31;
    if (gw >= NN) return;
    const int s = g_rowptr[gw];
    const int e = g_rowptr[gw + 1];
    const __half* base = (lane < 16) ? hhi : hlo;
    const int f0 = (lane & 15) * 8;
    float a[8];
#pragma unroll
    for (int q = 0; q < 8; q++) a[q] = 0.f;
    int j = s;
    for (; j + 1 < e; j += 2) {
        int s0 = g_srcs[j], s1 = g_srcs[j + 1];
        uint4 v0 = *(const uint4*)(base + (((size_t)s0) << 7) + f0);
        uint4 v1 = *(const uint4*)(base + (((size_t)s1) << 7) + f0);
        float2 p;
        p = upk(v0.x); a[0] += p.x; a[1] += p.y;
        p = upk(v0.y); a[2] += p.x; a[3] += p.y;
        p = upk(v0.z); a[4] += p.x; a[5] += p.y;
        p = upk(v0.w); a[6] += p.x; a[7] += p.y;
        p = upk(v1.x); a[0] += p.x; a[1] += p.y;
        p = upk(v1.y); a[2] += p.x; a[3] += p.y;
        p = upk(v1.z); a[4] += p.x; a[5] += p.y;
        p = upk(v1.w); a[6] += p.x; a[7] += p.y;
    }
    if (j < e) {
        uint4 v0 = *(const uint4*)(base + (((size_t)g_srcs[j]) << 7) + f0);
        float2 p;
        p = upk(v0.x); a[0] += p.x; a[1] += p.y;
        p = upk(v0.y); a[2] += p.x; a[3] += p.y;
        p = upk(v0.z); a[4] += p.x; a[5] += p.y;
        p = upk(v0.w); a[6] += p.x; a[7] += p.y;
    }
#pragma unroll
    for (int q = 0; q < 8; q++) a[q] += __shfl_xor_sync(0xffffffffu, a[q], 16);
    if (lane < 16) {
        float inv = 1.0f / (float)max(e - s, 1);
        __half h[8], l[8];
#pragma unroll
        for (int q = 0; q < 8; q++) split1(a[q] * inv, h[q], l[q]);
        size_t o = (((size_t)gw) << 7) + f0;
        *(uint4*)(ahi + o) = make_uint4(pack2(h[0], h[1]), pack2(h[2], h[3]),
                                        pack2(h[4], h[5]), pack2(h[6], h[7]));
        *(uint4*)(alo + o) = make_uint4(pack2(l[0], l[1]), pack2(l[2], l[3]),
                                        pack2(l[4], l[5]), pack2(l[6], l[7]));
    }
}

// ---------------------------- HMMA GEMM (fp16 2-term) ---------------------
// 128 threads (4 warps), warp tile 64 x (DOUT/2). K=256 as 8 stages of K=32
// (0-3: self/Ws, 4-7: agg/Wn), double-buffered cp.async, 80B row stride.
// A = fp16 hi+lo; B = single fp16. 2 MMA terms: Ahi*B + Alo*B.
// SPLIT_A: layer 1 self operand is fp32 x: LDG->split->STS.

template <int BM, int DOUT, bool RELU, bool SPLIT_OUT, bool SPLIT_A>
__global__ void __launch_bounds__(128, 2)
k_gemm2(const float* __restrict__ xf,
        const __half* __restrict__ ahi, const __half* __restrict__ alo,
        const __half* __restrict__ ghi, const __half* __restrict__ glo,
        const __half* __restrict__ ws, const __half* __restrict__ wn,
        const float* __restrict__ bias,
        float* __restrict__ outf,
        __half* __restrict__ ohi, __half* __restrict__ olo) {
    extern __shared__ char sm[];
    constexpr int NWM = BM / 64;
    constexpr int NWN = 4 / NWM;
    constexpr int WARP_N = DOUT / NWN;
    constexpr int NT = WARP_N / 8;
    constexpr int A_B = BM * 80;
    constexpr int B_B = DOUT * 80;
    constexpr int STG = 2 * A_B + B_B;

    const int tid = threadIdx.x, wid = tid >> 5, lane = tid & 31;
    const int wm = wid % NWM, wn2 = wid / NWM;
    const int row0 = blockIdx.x * BM;
    const uint32_t sb = smem_u32(sm);

    float acc[4][NT][4];
#pragma unroll
    for (int mt = 0; mt < 4; mt++)
#pragma unroll
        for (int nt = 0; nt < NT; nt++)
#pragma unroll
            for (int q = 0; q < 4; q++) acc[mt][nt][q] = 0.f;

    float xr[SPLIT_A ? 32 : 1];

    auto loadB = [&](int s, int p) {
        const int koff = (s & 3) * 32;
        const __half* B = (s < 4) ? ws : wn;
        const uint32_t bb = sb + p * STG + 2 * A_B;
#pragma unroll
        for (int i = 0; i < DOUT / 32; i++) {
            int c = i * 128 + tid;
            int r = c >> 2, kc = c & 3;
            size_t off = ((size_t)r << 7) + koff + kc * 8;
            cp16(bb + r * 80 + kc * 16, B + off, true);
        }
    };
    auto loadA = [&](int s, int p) {
        const int koff = (s & 3) * 32;
        const __half* Ah = (s < 4) ? ahi : ghi;
        const __half* Al = (s < 4) ? alo : glo;
        const uint32_t ah = sb + p * STG, al = ah + A_B;
#pragma unroll
        for (int i = 0; i < BM / 32; i++) {
            int c = i * 128 + tid;
            int r = c >> 2, kc = c & 3;
            bool v = (row0 + r) < NN;
            size_t off = ((size_t)(row0 + r) << 7) + koff + kc * 8;
            cp16(ah + r * 80 + kc * 16, Ah + off, v);
            cp16(al + r * 80 + kc * 16, Al + off, v);
        }
    };
    auto ldgA = [&](int s) {
        const int koff = (s & 3) * 32;
#pragma unroll
        for (int i = 0; i < 8; i++) {
            int c = i * 128 + tid;
            int r = c >> 3, q = c & 7;
            float4 t = make_float4(0.f, 0.f, 0.f, 0.f);
            if (row0 + r < NN)
                t = *(const float4*)(xf + ((size_t)(row0 + r) << 7) + koff + q * 4);
            xr[i * 4 + 0] = t.x; xr[i * 4 + 1] = t.y;
            xr[i * 4 + 2] = t.z; xr[i * 4 + 3] = t.w;
        }
    };
    auto stsA = [&](int p) {
        const uint32_t ah = sb + p * STG, al = ah + A_B;
#pragma unroll
        for (int i = 0; i < 8; i++) {
            int c = i * 128 + tid;
            int r = c >> 3, q = c & 7;
            __half h0, h1, h2, h3, l0, l1, l2, l3;
            split1(xr[i * 4 + 0], h0, l0); split1(xr[i * 4 + 1], h1, l1);
            split1(xr[i * 4 + 2], h2, l2); split1(xr[i * 4 + 3], h3, l3);
            uint32_t hh0 = pack2(h0, h1), hh1 = pack2(h2, h3);
            uint32_t ll0 = pack2(l0, l1), ll1 = pack2(l2, l3);
            uint32_t d = r * 80 + q * 8;
            asm volatile("st.shared.v2.b32 [%0], {%1,%2};" :: "r"(ah + d), "r"(hh0), "r"(hh1) : "memory");
            asm volatile("st.shared.v2.b32 [%0], {%1,%2};" :: "r"(al + d), "r"(ll0), "r"(ll1) : "memory");
        }
    };
    auto compute = [&](int p) {
#pragma unroll
        for (int ks = 0; ks < 2; ks++) {
            uint32_t ahf[4][4], alf[4][4];
#pragma unroll
            for (int mt = 0; mt < 4; mt++) {
                int r = wm * 64 + mt * 16 + (lane & 15);
                int kc = ks * 2 + (lane >> 4);
                uint32_t o = p * STG + (uint32_t)(r * 80) + (uint32_t)(kc * 16);
                ldsm_x4(ahf[mt], sb + o);
                ldsm_x4(alf[mt], sb + A_B + o);
            }
#pragma unroll
            for (int np = 0; np < NT / 2; np++) {
                int n = wn2 * WARP_N + np * 16 + (lane & 7) + ((lane >> 4) << 3);
                int kc = ks * 2 + ((lane >> 3) & 1);
                uint32_t o = p * STG + 2 * A_B + (uint32_t)(n * 80) + (uint32_t)(kc * 16);
                uint32_t bh[4];
                ldsm_x4(bh, sb + o);
#pragma unroll
                for (int mt = 0; mt < 4; mt++) {
                    mma_f16(acc[mt][2 * np],     ahf[mt], bh);
                    mma_f16(acc[mt][2 * np + 1], ahf[mt], bh + 2);
                }
#pragma unroll
                for (int mt = 0; mt < 4; mt++) {
                    mma_f16(acc[mt][2 * np],     alf[mt], bh);
                    mma_f16(acc[mt][2 * np + 1], alf[mt], bh + 2);
                }
            }
        }
    };

    loadB(0, 0);
    if (SPLIT_A) { ldgA(0); stsA(0); }
    else loadA(0, 0);
    CP_COMMIT();
    CP_WAIT0();
    __syncthreads();

    int p = 0;
#pragma unroll
    for (int s = 0; s < 8; s++) {
        const int sn = s + 1;
        if (sn < 8) {
            loadB(sn, p ^ 1);
            if (SPLIT_A && sn < 4) ldgA(sn);
            else loadA(sn, p ^ 1);
            CP_COMMIT();
        }
        compute(p);
        if (sn < 8) {
            if (SPLIT_A && sn < 4) stsA(p ^ 1);
            CP_WAIT0();
            __syncthreads();
            p ^= 1;
        }
    }

    const int g = lane >> 2, t = lane & 3;
#pragma unroll
    for (int mt = 0; mt < 4; mt++) {
        int r0 = row0 + wm * 64 + mt * 16 + g;
        int r1 = r0 + 8;
#pragma unroll
        for (int nt = 0; nt < NT; nt++) {
            int col = wn2 * WARP_N + nt * 8 + 2 * t;
            float b0 = __ldg(bias + col), b1 = __ldg(bias + col + 1);
            float c0 = acc[mt][nt][0] + b0, c1 = acc[mt][nt][1] + b1;
            float c2 = acc[mt][nt][2] + b0, c3 = acc[mt][nt][3] + b1;
            if (RELU) {
                c0 = fmaxf(c0, 0.f); c1 = fmaxf(c1, 0.f);
                c2 = fmaxf(c2, 0.f); c3 = fmaxf(c3, 0.f);
            }
            if (SPLIT_OUT) {
                __half h0, h1, l0, l1;
                if (r0 < NN) {
                    split1(c0, h0, l0); split1(c1, h1, l1);
                    size_t o = ((size_t)r0 << 7) + col;
                    *(uint32_t*)(ohi + o) = pack2(h0, h1);
                    *(uint32_t*)(olo + o) = pack2(l0, l1);
                }
                if (r1 < NN) {
                    split1(c2, h0, l0); split1(c3, h1, l1);
                    size_t o = ((size_t)r1 << 7) + col;
                    *(uint32_t*)(ohi + o) = pack2(h0, h1);
                    *(uint32_t*)(olo + o) = pack2(l0, l1);
                }
            } else {
                if (r0 < NN) *(float2*)(outf + (size_t)r0 * DOUT + col) = make_float2(c0, c1);
                if (r1 < NN) *(float2*)(outf + (size_t)r1 * DOUT + col) = make_float2(c2, c3);
            }
        }
    }
}

// ---------------------------------------------------------------------------

extern "C" void kernel_launch(void* const* d_in, const int* in_sizes, int n_in,
                              void* d_out, int out_size) {
    const float* x   = (const float*)d_in[0];
    const int* esrc  = (const int*)d_in[1];
    const int* edst  = (const int*)d_in[2];
    const float* Ws1 = (const float*)d_in[3];
    const float* Wn1 = (const float*)d_in[4];
    const float* b1  = (const float*)d_in[5];
    const float* Ws2 = (const float*)d_in[6];
    const float* Wn2 = (const float*)d_in[7];
    const float* b2  = (const float*)d_in[8];
    const float* Ws3 = (const float*)d_in[9];
    const float* Wn3 = (const float*)d_in[10];
    const float* b3  = (const float*)d_in[11];
    float* out = (float*)d_out;

    __half *s0hi, *s0lo, *s1hi, *s1lo, *aghi, *aglo, *wh;
    cudaGetSymbolAddress((void**)&s0hi, g_s0hi);
    cudaGetSymbolAddress((void**)&s0lo, g_s0lo);
    cudaGetSymbolAddress((void**)&s1hi, g_s1hi);
    cudaGetSymbolAddress((void**)&s1lo, g_s1lo);
    cudaGetSymbolAddress((void**)&aghi, g_agghi);
    cudaGetSymbolAddress((void**)&aglo, g_agglo);
    cudaGetSymbolAddress((void**)&wh, g_wh);

    int *cnt; unsigned long long *state;
    cudaGetSymbolAddress((void**)&cnt, g_cnt);
    cudaGetSymbolAddress((void**)&state, g_state);

    const int SMEM_12 = 2 * (2 * 128 * 80 + 128 * 80);  // 61440
    const int SMEM_3  = 2 * (2 * 128 * 80 + 64 * 80);   // 51200
    cudaFuncSetAttribute(k_gemm2<128, 128, true, true, true>,
                         cudaFuncAttributeMaxDynamicSharedMemorySize, SMEM_12);
    cudaFuncSetAttribute(k_gemm2<128, 128, true, true, false>,
                         cudaFuncAttributeMaxDynamicSharedMemorySize, SMEM_12);
    cudaFuncSetAttribute(k_gemm2<128, 64, false, false, false>,
                         cudaFuncAttributeMaxDynamicSharedMemorySize, SMEM_3);

    const int TB = 256;
    const int gridE2 = (NE / 2 + TB - 1) / TB;
    const int gridW = (NN * 32 + TB - 1) / TB;
    const int gridM = (NN + 127) / 128;  // 782

    // CSR build
    cudaMemsetAsync(cnt, 0, NN * sizeof(int));
    cudaMemsetAsync(state, 0, NB_SCAN * sizeof(unsigned long long));
    k_hist<<<gridE2, TB>>>(edst);                // kernel #1
    k_scan<<<NB_SCAN, 1024>>>();                 // kernel #2
    k_scatter<<<gridE2, TB>>>(esrc, edst);       // kernel #3

    // Layer-1 agg — kernel #4 (ncu capture slot)
    k_agg_f32<<<gridW, TB>>>(x, aghi, aglo);

    // weight convert (tiny)
    k_conv_w<<<(NWE / 4 + 127) / 128, 128>>>(Ws1, Wn1, Ws2, Wn2, Ws3, Wn3);

    // Layer 1 (SPLIT_A inline fp32 self path)
    k_gemm2<128, 128, true, true, true><<<gridM, 128, SMEM_12>>>(
        x, nullptr, nullptr, aghi, aglo,
        wh + WS1, wh + WN1, b1,
        nullptr, s1hi, s1lo);

    // Layer 2
    k_agg_split<<<gridW, TB>>>(s1hi, s1lo, aghi, aglo);
    k_gemm2<128, 128, true, true, false><<<gridM, 128, SMEM_12>>>(
        nullptr, s1hi, s1lo, aghi, aglo,
        wh + WS2, wh + WN2, b2,
        nullptr, s0hi, s0lo);

    // Layer 3 (fp32 out)
    k_agg_split<<<gridW, TB>>>(s0hi, s0lo, aghi, aglo);
    k_gemm2<128, 64, false, false, false><<<gridM, 128, SMEM_3>>>(
        nullptr, s0hi, s0lo, aghi, aglo,
        wh + WS3, wh + WN3, b3,
        out, nullptr, nullptr);
}